// round 1
// baseline (speedup 1.0000x reference)
#include <cuda_runtime.h>
#include <math.h>

#define BATCH 32
#define IMGH 112
#define IMGW 112
#define CC 96
#define NH 3
#define WS 7
#define SHIFT 3
#define NN 49          // WS*WS
#define HD 32          // CC/NH
#define NWIMG 256      // (112/7)^2
#define NWIN 8192      // BATCH*NWIMG
#define TOK 401408     // BATCH*IMGH*IMGW
#define HID 384
#define QKVC 288       // 3*CC

// ---------------- scratch ----------------
__device__ float g_qkv[(size_t)NWIN * NN * QKVC];   // 462 MB
__device__ float g_x1[(size_t)TOK * CC];            // 154 MB

// =====================================================================
// Kernel 1: gather shifted window + LN1 + QKV GEMM
// grid = NWIN blocks, 256 threads, dyn smem = (49*96 + 96*97)*4 = 56064 B
// =====================================================================
__global__ void __launch_bounds__(256) k_ln_qkv(
    const float* __restrict__ x,
    const float* __restrict__ n1g, const float* __restrict__ n1b,
    const float* __restrict__ qkv_w, const float* __restrict__ qkv_b)
{
    extern __shared__ float sm[];
    float* sA = sm;               // [49][96]
    float* sB = sm + NN * CC;     // [96][97]

    const int widx = blockIdx.x;
    const int b  = widx >> 8;          // /256
    const int wi = widx & 255;
    const int wh = wi >> 4;
    const int ww = wi & 15;
    const int tid = threadIdx.x;

    // gather (shifted window partition)
    for (int i = tid; i < NN * CC; i += 256) {
        int n = i / CC, c = i - n * CC;
        int r = n / WS, cc = n - r * WS;
        int sh = (wh * WS + r + SHIFT) % IMGH;
        int sw = (ww * WS + cc + SHIFT) % IMGW;
        int t = (b * IMGH + sh) * IMGW + sw;
        sA[i] = x[(size_t)t * CC + c];
    }
    __syncthreads();

    // LN1: warp per token
    const int lane = tid & 31;
    const int warp = tid >> 5;
    for (int n = warp; n < NN; n += 8) {
        float v0 = sA[n * CC + lane];
        float v1 = sA[n * CC + lane + 32];
        float v2 = sA[n * CC + lane + 64];
        float s = v0 + v1 + v2;
        float s2 = v0 * v0 + v1 * v1 + v2 * v2;
        #pragma unroll
        for (int o = 16; o > 0; o >>= 1) {
            s  += __shfl_xor_sync(0xffffffffu, s, o);
            s2 += __shfl_xor_sync(0xffffffffu, s2, o);
        }
        float m = s * (1.0f / CC);
        float var = s2 * (1.0f / CC) - m * m;
        float inv = rsqrtf(var + 1e-5f);
        sA[n * CC + lane]      = (v0 - m) * inv * n1g[lane]      + n1b[lane];
        sA[n * CC + lane + 32] = (v1 - m) * inv * n1g[lane + 32] + n1b[lane + 32];
        sA[n * CC + lane + 64] = (v2 - m) * inv * n1g[lane + 64] + n1b[lane + 64];
    }
    __syncthreads();

    // QKV GEMM: 3 tiles of 96 cols
    const int c = tid & 31;
    const int g8 = tid >> 5;
    float* qout = g_qkv + (size_t)widx * NN * QKVC;

    for (int ct = 0; ct < 3; ct++) {
        for (int i = tid; i < 96 * 96; i += 256) {
            int cl = i / 96, k = i - cl * 96;
            sB[k * 97 + cl] = qkv_w[(ct * 96 + cl) * 96 + k];
        }
        __syncthreads();

        float acc[6][3];
        float acc6[3] = {0.f, 0.f, 0.f};
        #pragma unroll
        for (int j = 0; j < 6; j++) { acc[j][0] = acc[j][1] = acc[j][2] = 0.f; }

        for (int k = 0; k < 96; k++) {
            float b0 = sB[k * 97 + c];
            float b1 = sB[k * 97 + c + 32];
            float b2 = sB[k * 97 + c + 64];
            #pragma unroll
            for (int j = 0; j < 6; j++) {
                float a = sA[(j * 8 + g8) * CC + k];
                acc[j][0] = fmaf(a, b0, acc[j][0]);
                acc[j][1] = fmaf(a, b1, acc[j][1]);
                acc[j][2] = fmaf(a, b2, acc[j][2]);
            }
            if (g8 == 0) {
                float a = sA[48 * CC + k];
                acc6[0] = fmaf(a, b0, acc6[0]);
                acc6[1] = fmaf(a, b1, acc6[1]);
                acc6[2] = fmaf(a, b2, acc6[2]);
            }
        }
        #pragma unroll
        for (int j = 0; j < 6; j++) {
            int n = j * 8 + g8;
            #pragma unroll
            for (int m = 0; m < 3; m++) {
                int col = ct * 96 + c + m * 32;
                qout[n * QKVC + col] = acc[j][m] + qkv_b[col];
            }
        }
        if (g8 == 0) {
            #pragma unroll
            for (int m = 0; m < 3; m++) {
                int col = ct * 96 + c + m * 32;
                qout[48 * QKVC + col] = acc6[m] + qkv_b[col];
            }
        }
        __syncthreads();
    }
}

// =====================================================================
// Kernel 2: attention + proj + residual
// grid = NWIN, 256 threads, dyn smem = 141520 B
// =====================================================================
#define SQ_PITCH 289
__global__ void __launch_bounds__(256) k_attn(
    const float* __restrict__ x,
    const float* __restrict__ attn_mask,
    const int*   __restrict__ rel_index,
    const float* __restrict__ rel_bias_table,
    const float* __restrict__ proj_w, const float* __restrict__ proj_b)
{
    extern __shared__ float sm[];
    float* sQ = sm;                             // [49][289]
    float* sS = sQ + NN * SQ_PITCH;             // [3*49*49]
    float* sO = sS + NH * NN * NN;              // [49][96]
    float* sW = sO + NN * CC;                   // [96][97]

    const int widx = blockIdx.x;
    const int b  = widx >> 8;
    const int wi = widx & 255;
    const int wh = wi >> 4;
    const int ww = wi & 15;
    const int tid = threadIdx.x;
    const int lane = tid & 31;
    const int warp = tid >> 5;

    const float* qkv = g_qkv + (size_t)widx * NN * QKVC;
    for (int i = tid; i < NN * QKVC; i += 256) {
        int n = i / QKVC, c = i - n * QKVC;
        sQ[n * SQ_PITCH + c] = qkv[i];
    }
    __syncthreads();

    // scores + bias + mask
    const float scale = 0.17677669529663689f;   // 1/sqrt(32)
    for (int idx = tid; idx < NH * NN * NN; idx += 256) {
        int h = idx / (NN * NN);
        int r = idx - h * NN * NN;
        int i = r / NN, j = r - i * NN;
        const float* qp = &sQ[i * SQ_PITCH + h * HD];
        const float* kp = &sQ[j * SQ_PITCH + CC + h * HD];
        float s = 0.f;
        #pragma unroll
        for (int d = 0; d < HD; d++) s = fmaf(qp[d], kp[d], s);
        s = s * scale
          + rel_bias_table[rel_index[r] * NH + h]
          + attn_mask[wi * NN * NN + r];
        sS[idx] = s;
    }
    __syncthreads();

    // softmax: warp per row (147 rows)
    for (int row = warp; row < NH * NN; row += 8) {
        float* rp = &sS[row * NN];
        float x0 = (lane < NN) ? rp[lane] : -1e30f;
        float x1 = (lane + 32 < NN) ? rp[lane + 32] : -1e30f;
        float mx = fmaxf(x0, x1);
        #pragma unroll
        for (int o = 16; o > 0; o >>= 1)
            mx = fmaxf(mx, __shfl_xor_sync(0xffffffffu, mx, o));
        float e0 = (lane < NN) ? __expf(x0 - mx) : 0.f;
        float e1 = (lane + 32 < NN) ? __expf(x1 - mx) : 0.f;
        float sum = e0 + e1;
        #pragma unroll
        for (int o = 16; o > 0; o >>= 1)
            sum += __shfl_xor_sync(0xffffffffu, sum, o);
        float inv = 1.0f / sum;
        if (lane < NN) rp[lane] = e0 * inv;
        if (lane + 32 < NN) rp[lane + 32] = e1 * inv;
    }
    __syncthreads();

    // attn @ V  -> sO[49][96]
    for (int idx = tid; idx < NN * CC; idx += 256) {
        int i = idx / CC, c = idx - i * CC;
        int h = c >> 5;
        const float* sp = &sS[(h * NN + i) * NN];
        float s = 0.f;
        #pragma unroll 7
        for (int j = 0; j < NN; j++)
            s = fmaf(sp[j], sQ[j * SQ_PITCH + 2 * CC + c], s);
        sO[idx] = s;
    }
    __syncthreads();

    // proj: stage weights, 3 cols/thread, 7 tokens
    for (int i = tid; i < 96 * 96; i += 256) {
        int cl = i / 96, k = i - cl * 96;
        sW[k * 97 + cl] = proj_w[cl * 96 + k];
    }
    __syncthreads();

    const int c = tid & 31;
    const int g8 = tid >> 5;
    float acc[6][3];
    float acc6[3] = {0.f, 0.f, 0.f};
    #pragma unroll
    for (int j = 0; j < 6; j++) { acc[j][0] = acc[j][1] = acc[j][2] = 0.f; }
    for (int k = 0; k < 96; k++) {
        float b0 = sW[k * 97 + c];
        float b1 = sW[k * 97 + c + 32];
        float b2 = sW[k * 97 + c + 64];
        #pragma unroll
        for (int j = 0; j < 6; j++) {
            float a = sO[(j * 8 + g8) * CC + k];
            acc[j][0] = fmaf(a, b0, acc[j][0]);
            acc[j][1] = fmaf(a, b1, acc[j][1]);
            acc[j][2] = fmaf(a, b2, acc[j][2]);
        }
        if (g8 == 0) {
            float a = sO[48 * CC + k];
            acc6[0] = fmaf(a, b0, acc6[0]);
            acc6[1] = fmaf(a, b1, acc6[1]);
            acc6[2] = fmaf(a, b2, acc6[2]);
        }
    }

    // scatter: residual add with source token (roll is self-inverse here)
    #pragma unroll
    for (int j = 0; j < 7; j++) {
        int n = j * 8 + g8;
        if (n > 48) break;
        float* accp = (j < 6) ? acc[j] : acc6;
        int r = n / WS, cc = n - r * WS;
        int sh = (wh * WS + r + SHIFT) % IMGH;
        int sw = (ww * WS + cc + SHIFT) % IMGW;
        int t = (b * IMGH + sh) * IMGW + sw;
        #pragma unroll
        for (int m = 0; m < 3; m++) {
            int col = c + m * 32;
            g_x1[(size_t)t * CC + col] = x[(size_t)t * CC + col] + accp[m] + proj_b[col];
        }
    }
}

// =====================================================================
// Kernel 3: LN2 + fc1 + GELU + fc2 + residual
// grid = TOK/64, 256 threads, dyn smem = 172544 B
// =====================================================================
__global__ void __launch_bounds__(256) k_mlp(
    const float* __restrict__ n2g, const float* __restrict__ n2b,
    const float* __restrict__ fc1_w, const float* __restrict__ fc1_b,
    const float* __restrict__ fc2_w, const float* __restrict__ fc2_b,
    float* __restrict__ out)
{
    extern __shared__ float sm[];
    float* sH = sm;                      // [64][384]
    float* sX = sm + 64 * HID;           // [64][96]
    float* sW = sX + 64 * CC;            // max(96*65, 128*97) floats

    const int tid = threadIdx.x;
    const int lane = tid & 31;
    const int warp = tid >> 5;
    const int t0 = blockIdx.x * 64;

    // LN2: warp per token
    for (int n = warp; n < 64; n += 8) {
        const float* xp = g_x1 + (size_t)(t0 + n) * CC;
        float v0 = xp[lane], v1 = xp[lane + 32], v2 = xp[lane + 64];
        float s = v0 + v1 + v2;
        float s2 = v0 * v0 + v1 * v1 + v2 * v2;
        #pragma unroll
        for (int o = 16; o > 0; o >>= 1) {
            s  += __shfl_xor_sync(0xffffffffu, s, o);
            s2 += __shfl_xor_sync(0xffffffffu, s2, o);
        }
        float m = s * (1.0f / CC);
        float var = s2 * (1.0f / CC) - m * m;
        float inv = rsqrtf(var + 1e-5f);
        sX[n * CC + lane]      = (v0 - m) * inv * n2g[lane]      + n2b[lane];
        sX[n * CC + lane + 32] = (v1 - m) * inv * n2g[lane + 32] + n2b[lane + 32];
        sX[n * CC + lane + 64] = (v2 - m) * inv * n2g[lane + 64] + n2b[lane + 64];
    }
    __syncthreads();

    const int c = tid & 31;
    const int g8 = tid >> 5;

    // fc1 + GELU: 6 tiles of 64 cols
    for (int ct = 0; ct < 6; ct++) {
        for (int i = tid; i < 64 * 96; i += 256) {
            int cl = i / 96, k = i - cl * 96;
            sW[k * 65 + cl] = fc1_w[(ct * 64 + cl) * 96 + k];
        }
        __syncthreads();
        float acc[8][2];
        #pragma unroll
        for (int j = 0; j < 8; j++) { acc[j][0] = acc[j][1] = 0.f; }
        for (int k = 0; k < 96; k++) {
            float b0 = sW[k * 65 + c];
            float b1 = sW[k * 65 + c + 32];
            #pragma unroll
            for (int j = 0; j < 8; j++) {
                float a = sX[(j * 8 + g8) * CC + k];
                acc[j][0] = fmaf(a, b0, acc[j][0]);
                acc[j][1] = fmaf(a, b1, acc[j][1]);
            }
        }
        #pragma unroll
        for (int j = 0; j < 8; j++) {
            int n = j * 8 + g8;
            #pragma unroll
            for (int m = 0; m < 2; m++) {
                int col = ct * 64 + c + m * 32;
                float v = acc[j][m] + fc1_b[col];
                sH[n * HID + col] = 0.5f * v * (1.0f + erff(v * 0.70710678118654752f));
            }
        }
        __syncthreads();
    }

    // fc2: 96 cols (3/thread), k staged in 3 chunks of 128
    float acc[8][3];
    #pragma unroll
    for (int j = 0; j < 8; j++) { acc[j][0] = acc[j][1] = acc[j][2] = 0.f; }
    for (int kt = 0; kt < 3; kt++) {
        for (int i = tid; i < 96 * 128; i += 256) {
            int cl = i / 128, kk = i - cl * 128;
            sW[kk * 97 + cl] = fc2_w[cl * HID + kt * 128 + kk];
        }
        __syncthreads();
        for (int kk = 0; kk < 128; kk++) {
            float b0 = sW[kk * 97 + c];
            float b1 = sW[kk * 97 + c + 32];
            float b2 = sW[kk * 97 + c + 64];
            #pragma unroll
            for (int j = 0; j < 8; j++) {
                float a = sH[(j * 8 + g8) * HID + kt * 128 + kk];
                acc[j][0] = fmaf(a, b0, acc[j][0]);
                acc[j][1] = fmaf(a, b1, acc[j][1]);
                acc[j][2] = fmaf(a, b2, acc[j][2]);
            }
        }
        __syncthreads();
    }
    #pragma unroll
    for (int j = 0; j < 8; j++) {
        int n = j * 8 + g8;
        size_t base = (size_t)(t0 + n) * CC;
        #pragma unroll
        for (int m = 0; m < 3; m++) {
            int col = c + m * 32;
            out[base + col] = g_x1[base + col] + acc[j][m] + fc2_b[col];
        }
    }
}

// =====================================================================
extern "C" void kernel_launch(void* const* d_in, const int* in_sizes, int n_in,
                              void* d_out, int out_size)
{
    const float* x       = (const float*)d_in[0];
    const float* mask    = (const float*)d_in[1];
    const int*   relidx  = (const int*)  d_in[2];
    const float* n1g     = (const float*)d_in[3];
    const float* n1b     = (const float*)d_in[4];
    const float* qkv_w   = (const float*)d_in[5];
    const float* qkv_b   = (const float*)d_in[6];
    const float* proj_w  = (const float*)d_in[7];
    const float* proj_b  = (const float*)d_in[8];
    const float* rbt     = (const float*)d_in[9];
    const float* n2g     = (const float*)d_in[10];
    const float* n2b     = (const float*)d_in[11];
    const float* fc1_w   = (const float*)d_in[12];
    const float* fc1_b   = (const float*)d_in[13];
    const float* fc2_w   = (const float*)d_in[14];
    const float* fc2_b   = (const float*)d_in[15];
    float* out = (float*)d_out;

    const int smem1 = (NN * CC + 96 * 97) * 4;                               // 56064
    const int smem2 = (NN * SQ_PITCH + NH * NN * NN + NN * CC + 96 * 97) * 4; // 141520
    const int smem3 = (64 * HID + 64 * CC + 128 * 97) * 4;                    // 172544

    cudaFuncSetAttribute(k_ln_qkv, cudaFuncAttributeMaxDynamicSharedMemorySize, smem1);
    cudaFuncSetAttribute(k_attn,   cudaFuncAttributeMaxDynamicSharedMemorySize, smem2);
    cudaFuncSetAttribute(k_mlp,    cudaFuncAttributeMaxDynamicSharedMemorySize, smem3);

    k_ln_qkv<<<NWIN, 256, smem1>>>(x, n1g, n1b, qkv_w, qkv_b);
    k_attn<<<NWIN, 256, smem2>>>(x, mask, relidx, rbt, proj_w, proj_b);
    k_mlp<<<TOK / 64, 256, smem3>>>(n2g, n2b, fc1_w, fc1_b, fc2_w, fc2_b, out);
}